// round 1
// baseline (speedup 1.0000x reference)
#include <cuda_runtime.h>
#include <math.h>

#define H       16
#define DM      1024
#define DK      64
#define NW      16384
#define NCHUNK  128     // n-chunks for w-pass (128 rows each)

// ---- scratch (static __device__ arrays; no allocation) ----
__device__ float g_q[DM];               // projected query
__device__ float g_a[H * DM];           // a[h][j] = sum_d q[h,d] * Wk[h*64+d, j]
__device__ float g_c[H];                // c[h]    = sum_d q[h,d] * bk[h*64+d]
__device__ float g_scores[H * NW];      // scores, softmax'd in place -> p
__device__ float g_wpart[NCHUNK][H * DM];
__device__ float g_w[H * DM];           // w[h][j] = sum_n p[h,n] * value[n,j]
__device__ float g_x[DM];               // attention output before Wo

__device__ __forceinline__ float warp_red(float v) {
#pragma unroll
    for (int o = 16; o; o >>= 1) v += __shfl_down_sync(0xffffffffu, v, o);
    return v;
}

// ------------------------------------------------------------------
// 1) q[i] = dot(query, Wq[i]) + bq[i].  grid 128 x 256 (warp per row)
// ------------------------------------------------------------------
__global__ void k_qproj(const float* __restrict__ query,
                        const float* __restrict__ Wq,
                        const float* __restrict__ bq) {
    __shared__ __align__(16) float qs[DM];
    const int tid = threadIdx.x;
    for (int i = tid; i < DM; i += 256) qs[i] = query[i];
    __syncthreads();
    const int w = tid >> 5, lane = tid & 31;
    const int row = blockIdx.x * 8 + w;
    const float4* wr = (const float4*)(Wq + (size_t)row * DM);
    const float4* q4 = (const float4*)qs;
    float acc = 0.f;
#pragma unroll 4
    for (int k = lane; k < DM / 4; k += 32) {
        float4 a = wr[k], b = q4[k];
        acc += a.x * b.x + a.y * b.y + a.z * b.z + a.w * b.w;
    }
    acc = warp_red(acc);
    if (lane == 0) g_q[row] = acc + bq[row];
}

// ------------------------------------------------------------------
// 2) a[h][j] = sum_d q[h*64+d]*Wk[h*64+d][j];  c[h] = sum_d q*bk
//    grid 16 (h) x 256
// ------------------------------------------------------------------
__global__ void k_aprep(const float* __restrict__ Wk,
                        const float* __restrict__ bk) {
    const int h = blockIdx.x, tid = threadIdx.x;
    __shared__ float qh[DK];
    if (tid < DK) qh[tid] = g_q[h * DK + tid];
    __syncthreads();
    float acc0 = 0.f, acc1 = 0.f, acc2 = 0.f, acc3 = 0.f;
    for (int d = 0; d < DK; d++) {
        const float qv = qh[d];
        const float* wr = Wk + (size_t)(h * DK + d) * DM;
        acc0 += qv * wr[tid];
        acc1 += qv * wr[tid + 256];
        acc2 += qv * wr[tid + 512];
        acc3 += qv * wr[tid + 768];
    }
    g_a[h * DM + tid]       = acc0;
    g_a[h * DM + tid + 256] = acc1;
    g_a[h * DM + tid + 512] = acc2;
    g_a[h * DM + tid + 768] = acc3;
    if (tid < 32) {
        float c = 0.f;
        for (int d = tid; d < DK; d += 32) c += qh[d] * bk[h * DK + d];
        c = warp_red(c);
        if (tid == 0) g_c[h] = c;
    }
}

// ------------------------------------------------------------------
// 3) scores[h][n] = dot(key[n], a[h]) + c[h]
//    grid 512 blocks x 256 threads; 32 rows/block; 8 j-tiles of 128.
//    key tile staged coalesced into padded SMEM; a broadcast from SMEM.
// ------------------------------------------------------------------
__global__ void k_scores(const float* __restrict__ key) {
    __shared__ __align__(16) float keytile[32 * 132];  // pad: f4-stride 33 (odd) -> conflict-free
    __shared__ __align__(16) float a_s[16 * 132];
    const int tid = threadIdx.x;
    const int w = tid >> 5, lane = tid & 31;
    const int n0 = blockIdx.x * 32;

    float acc[16];
#pragma unroll
    for (int h = 0; h < 16; h++) acc[h] = 0.f;

    const float4* key4 = (const float4*)key;
    const float4* ga4  = (const float4*)g_a;

    const int r_ld = tid >> 3;   // 0..31  (key stage: row)
    const int c4b  = tid & 7;    // 0..7   (key stage: f4 col base)
    const int h_ld = tid >> 4;   // 0..15  (a stage: head)
    const int c4a  = tid & 15;   // 0..15  (a stage: f4 col base)

    for (int t = 0; t < 8; t++) {
        // stage key tile: 32 rows x 128 floats, fully coalesced
#pragma unroll
        for (int k = 0; k < 4; k++) {
            const int c4 = c4b + 8 * k;  // 0..31
            float4 v = key4[(size_t)(n0 + r_ld) * 256 + t * 32 + c4];
            *(float4*)&keytile[r_ld * 132 + c4 * 4] = v;
        }
        // stage a tile: 16 x 128
#pragma unroll
        for (int k = 0; k < 2; k++) {
            const int c4 = c4a + 16 * k;  // 0..31
            float4 v = ga4[h_ld * 256 + t * 32 + c4];
            *(float4*)&a_s[h_ld * 132 + c4 * 4] = v;
        }
        __syncthreads();
        // compute: warp w covers 16 of the 128 tile columns; lane = row
#pragma unroll
        for (int q = 0; q < 4; q++) {
            const int j = w * 16 + q * 4;
            const float4 kv = *(const float4*)&keytile[lane * 132 + j];
#pragma unroll
            for (int h = 0; h < 16; h++) {
                const float4 av = *(const float4*)&a_s[h * 132 + j];  // broadcast
                acc[h] += kv.x * av.x + kv.y * av.y + kv.z * av.z + kv.w * av.w;
            }
        }
        __syncthreads();
    }

    // cross-warp reduction (reuse keytile: 16*8*32 = 4096 <= 4224 floats)
    float* red = keytile;
#pragma unroll
    for (int h = 0; h < 16; h++) red[h * 256 + w * 32 + lane] = acc[h];
    __syncthreads();
    const int h0 = tid >> 5;   // 0..7
    const int r  = tid & 31;
#pragma unroll
    for (int s = 0; s < 2; s++) {
        const int hh = h0 + 8 * s;
        float v = g_c[hh];
#pragma unroll
        for (int ww = 0; ww < 8; ww++) v += red[hh * 256 + ww * 32 + r];
        g_scores[hh * NW + n0 + r] = v;
    }
}

// ------------------------------------------------------------------
// 4) softmax over n, per head. grid 16 x 256. In place.
// ------------------------------------------------------------------
__global__ void k_softmax() {
    const int h = blockIdx.x, tid = threadIdx.x;
    float* s = g_scores + (size_t)h * NW;
    __shared__ float sm[256];

    float mx = -1e30f;
    for (int i = tid; i < NW; i += 256) mx = fmaxf(mx, s[i]);
    sm[tid] = mx; __syncthreads();
    for (int o = 128; o; o >>= 1) {
        if (tid < o) sm[tid] = fmaxf(sm[tid], sm[tid + o]);
        __syncthreads();
    }
    mx = sm[0]; __syncthreads();

    float sum = 0.f;
    for (int i = tid; i < NW; i += 256) {
        const float e = expf(s[i] - mx);
        s[i] = e; sum += e;
    }
    sm[tid] = sum; __syncthreads();
    for (int o = 128; o; o >>= 1) {
        if (tid < o) sm[tid] += sm[tid + o];
        __syncthreads();
    }
    const float inv = 1.0f / sm[0];
    for (int i = tid; i < NW; i += 256) s[i] *= inv;
}

// ------------------------------------------------------------------
// 5) w partials: wpart[c][h][j] = sum_{n in chunk c} p[h][n]*value[n][j]
//    grid 512 = (4 j-quarters x 128 chunks) x 64 threads.
//    Thread owns one float4 of j; value loads fully coalesced;
//    p broadcast from SMEM; 16 x float4 accumulators in registers.
// ------------------------------------------------------------------
__global__ void k_wpass(const float* __restrict__ value) {
    __shared__ float p_s[H * 128];
    const int tid = threadIdx.x;            // 0..63
    const int jq = blockIdx.x & 3;
    const int chunk = blockIdx.x >> 2;      // 0..127
    const int n0 = chunk * 128;

    for (int i = tid; i < H * 128; i += 64) {
        const int h = i >> 7, n = i & 127;
        p_s[i] = g_scores[h * NW + n0 + n];
    }
    __syncthreads();

    float4 acc[H];
#pragma unroll
    for (int h = 0; h < H; h++) acc[h] = make_float4(0.f, 0.f, 0.f, 0.f);

    const float4* v4 = (const float4*)value;
    const int jf = jq * 64 + tid;           // 0..255 (f4 index)

#pragma unroll 2
    for (int n = 0; n < 128; n++) {
        const float4 v = v4[(size_t)(n0 + n) * 256 + jf];
#pragma unroll
        for (int h = 0; h < H; h++) {
            const float p = p_s[h * 128 + n];   // broadcast
            acc[h].x += p * v.x; acc[h].y += p * v.y;
            acc[h].z += p * v.z; acc[h].w += p * v.w;
        }
    }
    float4* wp = (float4*)&g_wpart[chunk][0];
#pragma unroll
    for (int h = 0; h < H; h++) wp[h * 256 + jf] = acc[h];
}

// ------------------------------------------------------------------
// 6) w[i] = sum_c wpart[c][i].  grid 64 x 256. Fixed order.
// ------------------------------------------------------------------
__global__ void k_wreduce() {
    const int i = blockIdx.x * 256 + threadIdx.x;  // < 16384
    float acc = 0.f;
#pragma unroll 8
    for (int c = 0; c < NCHUNK; c++) acc += g_wpart[c][i];
    g_w[i] = acc;
}

// ------------------------------------------------------------------
// 7) x[i] = dot(w[h], Wv[i]) + bv[i], h = i/64.  grid 128 x 256.
//    Each block covers 8 rows of the SAME head -> cache w_h in SMEM.
// ------------------------------------------------------------------
__global__ void k_xproj(const float* __restrict__ Wv,
                        const float* __restrict__ bv) {
    __shared__ __align__(16) float ws[DM];
    const int tid = threadIdx.x;
    const int h = blockIdx.x >> 3;              // rows b*8..b*8+7 share head
    for (int i = tid; i < DM; i += 256) ws[i] = g_w[h * DM + i];
    __syncthreads();
    const int w = tid >> 5, lane = tid & 31;
    const int row = blockIdx.x * 8 + w;
    const float4* wr = (const float4*)(Wv + (size_t)row * DM);
    const float4* q4 = (const float4*)ws;
    float acc = 0.f;
#pragma unroll 4
    for (int k = lane; k < DM / 4; k += 32) {
        float4 a = wr[k], b = q4[k];
        acc += a.x * b.x + a.y * b.y + a.z * b.z + a.w * b.w;
    }
    acc = warp_red(acc);
    if (lane == 0) g_x[row] = acc + bv[row];
}

// ------------------------------------------------------------------
// 8) out[i] = dot(x, Wo[i]) + bo[i].  grid 128 x 256.
// ------------------------------------------------------------------
__global__ void k_out(const float* __restrict__ Wo,
                      const float* __restrict__ bo,
                      float* __restrict__ out) {
    __shared__ __align__(16) float xs[DM];
    const int tid = threadIdx.x;
    for (int i = tid; i < DM; i += 256) xs[i] = g_x[i];
    __syncthreads();
    const int w = tid >> 5, lane = tid & 31;
    const int row = blockIdx.x * 8 + w;
    const float4* wr = (const float4*)(Wo + (size_t)row * DM);
    const float4* q4 = (const float4*)xs;
    float acc = 0.f;
#pragma unroll 4
    for (int k = lane; k < DM / 4; k += 32) {
        float4 a = wr[k], b = q4[k];
        acc += a.x * b.x + a.y * b.y + a.z * b.z + a.w * b.w;
    }
    acc = warp_red(acc);
    if (lane == 0) out[row] = acc + bo[row];
}

// ------------------------------------------------------------------
extern "C" void kernel_launch(void* const* d_in, const int* in_sizes, int n_in,
                              void* d_out, int out_size) {
    (void)in_sizes; (void)n_in; (void)out_size;
    const float* query = (const float*)d_in[0];
    const float* key   = (const float*)d_in[1];
    const float* value = (const float*)d_in[2];
    const float* Wq    = (const float*)d_in[3];
    const float* bq    = (const float*)d_in[4];
    const float* Wk    = (const float*)d_in[5];
    const float* bk    = (const float*)d_in[6];
    const float* Wv    = (const float*)d_in[7];
    const float* bv    = (const float*)d_in[8];
    const float* Wo    = (const float*)d_in[9];
    const float* bo    = (const float*)d_in[10];
    float* out = (float*)d_out;

    k_qproj  <<<128, 256>>>(query, Wq, bq);
    k_aprep  <<<H,   256>>>(Wk, bk);
    k_scores <<<NW / 32, 256>>>(key);
    k_softmax<<<H,   256>>>();
    k_wpass  <<<4 * NCHUNK, 64>>>(value);
    k_wreduce<<<64,  256>>>();
    k_xproj  <<<128, 256>>>(Wv, bv);
    k_out    <<<128, 256>>>(Wo, bo, out);
}